// round 7
// baseline (speedup 1.0000x reference)
#include <cuda_runtime.h>
#include <cuda_bf16.h>
#include <cstdint>
#include <string.h>

// Problem constants
#define NPTS   32768          // 8*4096 points (contiguous output dim)
#define NROWS  4096           // 64*64 coefficient rows
#define NBASIS 23
#define KPACK  80             // 3 blocks of 23 + pad(11), 5 k-steps of 16

// Split-bf16 operands, row-major [KPACK] per row/point (160 B, 16B-aligned).
// Pairing trick: a K-dot of these layouts = hi.hi + hi.lo + lo.hi  (lo.lo
// omitted, ~2^-18 relative):
//   coeff row: [ hi(0..22) | hi(0..22) | lo(0..22) | 0 ]
//   poly  row: [ hi(0..22) | lo(0..22) | hi(0..22) | 0 ]
__device__ __align__(16) __nv_bfloat16 g_polyb [(size_t)NPTS  * KPACK];
__device__ __align__(16) __nv_bfloat16 g_coefb [(size_t)NROWS * KPACK];

// ---------------------------------------------------------------------------
// Kernel 1: hydrogen basis (fp32 math validated at rel_err 1.2e-7 in R2),
// emitted as split bf16 [hi | lo | hi] rows.
// ---------------------------------------------------------------------------
__global__ void basis_kernel(const float* __restrict__ pos) {
    int p = blockIdx.x * blockDim.x + threadIdx.x;
    if (p >= NPTS) return;

    float x = pos[3 * p + 0], y = pos[3 * p + 1], z = pos[3 * p + 2];
    float r    = sqrtf(x * x + y * y + z * z) + 1e-12f;
    float invr = 1.0f / r;
    float xs = x * invr, ys = y * invr, ct = z * invr;

    float e1 = expf(-r), e2 = expf(-0.5f * r);
    float e3 = expf(-r * (1.0f / 3.0f)), e4 = expf(-0.25f * r);

    const float C00 = 0.28209479177387814f;
    const float K10 = 0.4886025119029199f;
    const float C21 = 1.0925484305920792f;
    const float C22 = 0.5462742152960396f;
    const float C20 = 0.31539156525252005f;

    float Y1m1 = -K10 * ys, Y10 = K10 * ct, Y1p1 = -K10 * xs;
    float Y2m2 =  C21 * xs * ys;
    float Y2m1 = -C21 * ys * ct;
    float Y20  =  C20 * (3.0f * ct * ct - 1.0f);
    float Y2p1 = -C21 * xs * ct;
    float Y2p2 =  C22 * (xs * xs - ys * ys);

    float R10 = 2.0f * e1;
    float R20 = 0.35355339059327373f * e2 * (2.0f - r);
    float R21 = 0.2041241452319315f  * e2 * r;

    float rho3 = (2.0f / 3.0f) * r;
    float R30 = 0.1283000598199168f   * e3 * (3.0f - 3.0f * rho3 + 0.5f * rho3 * rho3);
    float R31 = 0.045360921162019494f * e3 * rho3 * (4.0f - rho3);
    float R32 = 0.02028602242947916f  * e3 * rho3 * rho3;

    float rho4 = 0.5f * r;
    float R40 = 0.0625f * e4 *
                (4.0f - 6.0f * rho4 + 2.0f * rho4 * rho4 - rho4 * rho4 * rho4 * (1.0f / 6.0f));
    float R41 = 0.016137430609197573f * e4 * rho4 * (10.0f - 5.0f * rho4 + 0.5f * rho4 * rho4);
    float R42 = 0.004658474194686761f * e4 * rho4 * rho4 * (6.0f - rho4);

    float v[NBASIS];
    v[0]  = R10 * C00;
    v[1]  = R20 * C00;
    v[2]  = R21 * Y1m1;  v[3]  = R21 * Y10;  v[4]  = R21 * Y1p1;
    v[5]  = R30 * C00;
    v[6]  = R31 * Y1m1;  v[7]  = R31 * Y10;  v[8]  = R31 * Y1p1;
    v[9]  = R32 * Y2m2;  v[10] = R32 * Y2m1; v[11] = R32 * Y20;
    v[12] = R32 * Y2p1;  v[13] = R32 * Y2p2;
    v[14] = R40 * C00;
    v[15] = R41 * Y1m1;  v[16] = R41 * Y10;  v[17] = R41 * Y1p1;
    v[18] = R42 * Y2m2;  v[19] = R42 * Y2m1; v[20] = R42 * Y20;
    v[21] = R42 * Y2p1;  v[22] = R42 * Y2p2;

    __nv_bfloat16 row[KPACK];
#pragma unroll
    for (int k = 0; k < KPACK; k++) row[k] = __float2bfloat16(0.0f);
#pragma unroll
    for (int k = 0; k < NBASIS; k++) {
        __nv_bfloat16 h  = __float2bfloat16(v[k]);
        __nv_bfloat16 lo = __float2bfloat16(v[k] - __bfloat162float(h));
        row[k]              = h;    // block 0: hi
        row[NBASIS + k]     = lo;   // block 1: lo  (pairs with coeff hi)
        row[2 * NBASIS + k] = h;    // block 2: hi  (pairs with coeff lo)
    }
    uint4* dst = reinterpret_cast<uint4*>(g_polyb + (size_t)p * KPACK);
    const uint4* src = reinterpret_cast<const uint4*>(row);
#pragma unroll
    for (int i = 0; i < KPACK / 8; i++) dst[i] = src[i];
}

// ---------------------------------------------------------------------------
// Kernel 1b: coefficient split -> [hi | hi | lo] rows.
// ---------------------------------------------------------------------------
__global__ void coeff_split_kernel(const float* __restrict__ coeff) {
    int rw = blockIdx.x * blockDim.x + threadIdx.x;
    if (rw >= NROWS) return;
    __nv_bfloat16 row[KPACK];
#pragma unroll
    for (int k = 0; k < KPACK; k++) row[k] = __float2bfloat16(0.0f);
#pragma unroll
    for (int k = 0; k < NBASIS; k++) {
        float c = coeff[rw * NBASIS + k];
        __nv_bfloat16 h  = __float2bfloat16(c);
        __nv_bfloat16 lo = __float2bfloat16(c - __bfloat162float(h));
        row[k]              = h;    // block 0: hi
        row[NBASIS + k]     = h;    // block 1: hi
        row[2 * NBASIS + k] = lo;   // block 2: lo
    }
    uint4* dst = reinterpret_cast<uint4*>(g_coefb + (size_t)rw * KPACK);
    const uint4* src = reinterpret_cast<const uint4*>(row);
#pragma unroll
    for (int i = 0; i < KPACK / 8; i++) dst[i] = src[i];
}

// ---------------------------------------------------------------------------
// Kernel 2: mma.sync bf16 GEMM (PTX-portable under compute_103).
//   out[row][pt] = K-dot(coefb[row], polyb[pt]), K = 80.
//   CTA 256 thr = 8 warps (4 row-groups x 2 pt-groups); CTA tile 128x128;
//   warp tile 32 rows x 64 pts; m16n8k16, 5 k-steps; fragments straight from
//   gmem (operands L2-resident: 5.25 MB + 640 KB). Streaming stores.
// ---------------------------------------------------------------------------
__device__ __forceinline__ void mma_bf16(float* c, const uint32_t* a, const uint32_t* b) {
    asm volatile(
        "mma.sync.aligned.m16n8k16.row.col.f32.bf16.bf16.f32 "
        "{%0,%1,%2,%3}, {%4,%5,%6,%7}, {%8,%9}, {%0,%1,%2,%3};"
        : "+f"(c[0]), "+f"(c[1]), "+f"(c[2]), "+f"(c[3])
        : "r"(a[0]), "r"(a[1]), "r"(a[2]), "r"(a[3]), "r"(b[0]), "r"(b[1]));
}

__global__ __launch_bounds__(256, 2) void mma_kernel(float* __restrict__ out) {
    int lane = threadIdx.x & 31;
    int warp = threadIdx.x >> 5;
    int g  = lane >> 2;        // 0..7
    int t4 = lane & 3;         // 0..3
    int wr = warp >> 1;        // 0..3 row-group
    int wc = warp & 1;         // 0..1 pt-group

    int R0 = blockIdx.y * 128 + wr * 32;   // coefficient-row base
    int P0 = blockIdx.x * 128 + wc * 64;   // point base

    const __nv_bfloat16* __restrict__ A = g_coefb;
    const __nv_bfloat16* __restrict__ B = g_polyb;

    float c[2][8][4];
#pragma unroll
    for (int mt = 0; mt < 2; mt++)
#pragma unroll
        for (int nt = 0; nt < 8; nt++)
#pragma unroll
            for (int i = 0; i < 4; i++) c[mt][nt][i] = 0.0f;

#pragma unroll
    for (int s = 0; s < 5; s++) {
        int kb = s * 16 + 2 * t4;

        // A fragments for this k-step (L1-resident broadcast loads).
        uint32_t a[2][4];
#pragma unroll
        for (int mt = 0; mt < 2; mt++) {
            int r = R0 + mt * 16 + g;
            const uint32_t* p0 = reinterpret_cast<const uint32_t*>(A + (size_t)r * KPACK + kb);
            const uint32_t* p1 = reinterpret_cast<const uint32_t*>(A + (size_t)(r + 8) * KPACK + kb);
            a[mt][0] = p0[0];   // (row g,   k..k+1)
            a[mt][1] = p1[0];   // (row g+8, k..k+1)
            a[mt][2] = p0[4];   // (row g,   k+8..k+9)
            a[mt][3] = p1[4];   // (row g+8, k+8..k+9)
        }

        uint32_t b[8][2];
#pragma unroll
        for (int nt = 0; nt < 8; nt++) {
            int n = P0 + nt * 8 + g;
            const uint32_t* pb = reinterpret_cast<const uint32_t*>(B + (size_t)n * KPACK + kb);
            b[nt][0] = pb[0];   // (k..k+1,   n)
            b[nt][1] = pb[4];   // (k+8..k+9, n)
        }

#pragma unroll
        for (int mt = 0; mt < 2; mt++)
#pragma unroll
            for (int nt = 0; nt < 8; nt++)
                mma_bf16(c[mt][nt], a[mt], b[nt]);
    }

    // Epilogue: c0,c1 -> (row g, cols 2t4+{0,1}); c2,c3 -> (row g+8).
#pragma unroll
    for (int mt = 0; mt < 2; mt++) {
#pragma unroll
        for (int nt = 0; nt < 8; nt++) {
            float* o = out + (size_t)(R0 + mt * 16 + g) * NPTS + P0 + nt * 8 + 2 * t4;
            __stcs(reinterpret_cast<float2*>(o),
                   make_float2(c[mt][nt][0], c[mt][nt][1]));
            __stcs(reinterpret_cast<float2*>(o + (size_t)8 * NPTS),
                   make_float2(c[mt][nt][2], c[mt][nt][3]));
        }
    }
}

// ---------------------------------------------------------------------------
// Launch: [0] position (8*4096*3 f32), [1] coefficients (64*64*23 f32).
// Output: (64,64,8,4096) f32 = out[row][point].
// ---------------------------------------------------------------------------
extern "C" void kernel_launch(void* const* d_in, const int* in_sizes, int n_in,
                              void* d_out, int out_size) {
    const float* pos   = (const float*)d_in[0];
    const float* coeff = (const float*)d_in[1];
    float* out = (float*)d_out;

    basis_kernel<<<NPTS / 256, 256>>>(pos);
    coeff_split_kernel<<<NROWS / 256, 256>>>(coeff);

    dim3 grid(NPTS / 128, NROWS / 128);   // (256, 32)
    mma_kernel<<<grid, 256>>>(out);
}

// round 8
// speedup vs baseline: 1.4604x; 1.4604x over previous
#include <cuda_runtime.h>
#include <cuda_bf16.h>
#include <string.h>

// Problem constants (static shapes from the reference)
#define NPTS   32768          // 8 * 4096 points (contiguous in output)
#define NROWS  4096           // 64 * 64 (m,n) pairs
#define NBASIS 23

// Scratch: poly[k][p], k-major so GEMM-side loads are coalesced float4.
__device__ float g_poly[NBASIS * NPTS];

// ---------------------------------------------------------------------------
// Kernel 1: per-point hydrogen wavefunction basis (validated rel_err 1.2e-7).
// ---------------------------------------------------------------------------
__global__ void basis_kernel(const float* __restrict__ pos) {
    int p = blockIdx.x * blockDim.x + threadIdx.x;
    if (p >= NPTS) return;

    float x = pos[3 * p + 0], y = pos[3 * p + 1], z = pos[3 * p + 2];
    float r    = sqrtf(x * x + y * y + z * z) + 1e-12f;
    float invr = 1.0f / r;
    float xs = x * invr, ys = y * invr, ct = z * invr;

    float e1 = expf(-r), e2 = expf(-0.5f * r);
    float e3 = expf(-r * (1.0f / 3.0f)), e4 = expf(-0.25f * r);

    const float C00 = 0.28209479177387814f;
    const float K10 = 0.4886025119029199f;
    const float C21 = 1.0925484305920792f;
    const float C22 = 0.5462742152960396f;
    const float C20 = 0.31539156525252005f;

    float Y1m1 = -K10 * ys, Y10 = K10 * ct, Y1p1 = -K10 * xs;
    float Y2m2 =  C21 * xs * ys;
    float Y2m1 = -C21 * ys * ct;
    float Y20  =  C20 * (3.0f * ct * ct - 1.0f);
    float Y2p1 = -C21 * xs * ct;
    float Y2p2 =  C22 * (xs * xs - ys * ys);

    float R10 = 2.0f * e1;
    float R20 = 0.35355339059327373f * e2 * (2.0f - r);
    float R21 = 0.2041241452319315f  * e2 * r;

    float rho3 = (2.0f / 3.0f) * r;
    float R30 = 0.1283000598199168f   * e3 * (3.0f - 3.0f * rho3 + 0.5f * rho3 * rho3);
    float R31 = 0.045360921162019494f * e3 * rho3 * (4.0f - rho3);
    float R32 = 0.02028602242947916f  * e3 * rho3 * rho3;

    float rho4 = 0.5f * r;
    float R40 = 0.0625f * e4 *
                (4.0f - 6.0f * rho4 + 2.0f * rho4 * rho4 - rho4 * rho4 * rho4 * (1.0f / 6.0f));
    float R41 = 0.016137430609197573f * e4 * rho4 * (10.0f - 5.0f * rho4 + 0.5f * rho4 * rho4);
    float R42 = 0.004658474194686761f * e4 * rho4 * rho4 * (6.0f - rho4);

    float v[NBASIS];
    v[0]  = R10 * C00;
    v[1]  = R20 * C00;
    v[2]  = R21 * Y1m1;  v[3]  = R21 * Y10;  v[4]  = R21 * Y1p1;
    v[5]  = R30 * C00;
    v[6]  = R31 * Y1m1;  v[7]  = R31 * Y10;  v[8]  = R31 * Y1p1;
    v[9]  = R32 * Y2m2;  v[10] = R32 * Y2m1; v[11] = R32 * Y20;
    v[12] = R32 * Y2p1;  v[13] = R32 * Y2p2;
    v[14] = R40 * C00;
    v[15] = R41 * Y1m1;  v[16] = R41 * Y10;  v[17] = R41 * Y1p1;
    v[18] = R42 * Y2m2;  v[19] = R42 * Y2m1; v[20] = R42 * Y20;
    v[21] = R42 * Y2p1;  v[22] = R42 * Y2p2;

#pragma unroll
    for (int k = 0; k < NBASIS; k++) g_poly[k * NPTS + p] = v[k];
}

// ---------------------------------------------------------------------------
// Kernel 2: out(4096 x 32768) = coeff(4096 x 23) @ poly(23 x 32768)
// f32x2 GEMM, fma-pipe-limited by design:
//   - coefficients staged in smem NON-duplicated, 24 floats/row
//     -> 6 broadcast LDS.128 per row (12 L1TEX wavefronts, was 24)
//   - {c,c} f32x2 pairs formed by register MOVs on the ALU pipe (46 cyc/row,
//     hidden under 92 fma-pipe cyc/row)
//   - each thread: 4 consecutive points, poly in 92 regs, STG.128 streaming
// ---------------------------------------------------------------------------
#define TPB   256
#define PT    1024   // points per block (TPB * 4)
#define RT    128    // coefficient rows per block
#define CW    24     // floats per smem coeff row (23 + pad)

__device__ __forceinline__ float2 fma2(float2 a, float2 b, float2 c) {
    unsigned long long ua, ub, uc;
    memcpy(&ua, &a, 8); memcpy(&ub, &b, 8); memcpy(&uc, &c, 8);
    asm("fma.rn.f32x2 %0, %1, %2, %0;" : "+l"(uc) : "l"(ua), "l"(ub));
    float2 d; memcpy(&d, &uc, 8);
    return d;
}

__global__ __launch_bounds__(TPB, 2) void gemm_kernel(const float* __restrict__ coeff,
                                                      float* __restrict__ out) {
    __shared__ float cs[RT * CW];   // 12 KB, non-duplicated

    int tid = threadIdx.x;
    int p0  = blockIdx.x * PT + tid * 4;
    int r0  = blockIdx.y * RT;

    // Stage coefficient tile (scalar floats, row padded to 24).
    for (int i = tid; i < RT * CW; i += TPB) {
        int rr = i / CW;
        int k  = i - rr * CW;
        cs[i] = (k < NBASIS) ? coeff[(r0 + rr) * NBASIS + k] : 0.0f;
    }

    // Poly columns for this thread's 4 points, as aligned f32x2 halves.
    float2 pxy[NBASIS], pzw[NBASIS];
#pragma unroll
    for (int k = 0; k < NBASIS; k++) {
        float4 t = *reinterpret_cast<const float4*>(&g_poly[k * NPTS + p0]);
        pxy[k] = make_float2(t.x, t.y);
        pzw[k] = make_float2(t.z, t.w);
    }
    __syncthreads();

    float* outp = out + (size_t)r0 * NPTS + p0;
#pragma unroll 2
    for (int rr = 0; rr < RT; ++rr) {
        const float4* crow = reinterpret_cast<const float4*>(cs + rr * CW);
        float2 a0 = make_float2(0.0f, 0.0f);
        float2 a1 = make_float2(0.0f, 0.0f);
#pragma unroll
        for (int q = 0; q < 5; q++) {            // coeffs 0..19: 5 x LDS.128
            float4 c4 = crow[q];                 // broadcast, 4 scalar coeffs
            float2 c0 = make_float2(c4.x, c4.x); // reg-dup on alu pipe
            float2 c1 = make_float2(c4.y, c4.y);
            float2 c2 = make_float2(c4.z, c4.z);
            float2 c3 = make_float2(c4.w, c4.w);
            a0 = fma2(c0, pxy[4 * q + 0], a0);  a1 = fma2(c0, pzw[4 * q + 0], a1);
            a0 = fma2(c1, pxy[4 * q + 1], a0);  a1 = fma2(c1, pzw[4 * q + 1], a1);
            a0 = fma2(c2, pxy[4 * q + 2], a0);  a1 = fma2(c2, pzw[4 * q + 2], a1);
            a0 = fma2(c3, pxy[4 * q + 3], a0);  a1 = fma2(c3, pzw[4 * q + 3], a1);
        }
        {                                        // coeffs 20..22: last LDS.128
            float4 c4 = crow[5];
            float2 c0 = make_float2(c4.x, c4.x);
            float2 c1 = make_float2(c4.y, c4.y);
            float2 c2 = make_float2(c4.z, c4.z);
            a0 = fma2(c0, pxy[20], a0);  a1 = fma2(c0, pzw[20], a1);
            a0 = fma2(c1, pxy[21], a0);  a1 = fma2(c1, pzw[21], a1);
            a0 = fma2(c2, pxy[22], a0);  a1 = fma2(c2, pzw[22], a1);
        }
        float4 o = make_float4(a0.x, a0.y, a1.x, a1.y);
        __stcs(reinterpret_cast<float4*>(outp), o);   // streaming STG.128
        outp += NPTS;
    }
}

// ---------------------------------------------------------------------------
// Launch: [0] position (8*4096*3 f32), [1] coefficients (64*64*23 f32).
// Output: (64,64,8,4096) f32 = out[row][point].
// ---------------------------------------------------------------------------
extern "C" void kernel_launch(void* const* d_in, const int* in_sizes, int n_in,
                              void* d_out, int out_size) {
    const float* pos   = (const float*)d_in[0];
    const float* coeff = (const float*)d_in[1];
    float* out = (float*)d_out;

    basis_kernel<<<NPTS / 256, 256>>>(pos);

    dim3 grid(NPTS / PT, NROWS / RT);   // (32, 32)
    gemm_kernel<<<grid, TPB>>>(coeff, out);
}

// round 9
// speedup vs baseline: 1.4608x; 1.0003x over previous
#include <cuda_runtime.h>
#include <cuda_bf16.h>
#include <string.h>

// Problem constants (static shapes from the reference)
#define NPTS   32768          // 8 * 4096 points (contiguous in output)
#define NROWS  4096           // 64 * 64 (m,n) pairs
#define NBASIS 23

// Scratch: poly[k][p], k-major so GEMM-side loads are coalesced.
__device__ float g_poly[NBASIS * NPTS];

// ---------------------------------------------------------------------------
// Kernel 1: per-point hydrogen wavefunction basis (validated rel_err 1.2e-7).
// ---------------------------------------------------------------------------
__global__ void basis_kernel(const float* __restrict__ pos) {
    int p = blockIdx.x * blockDim.x + threadIdx.x;
    if (p >= NPTS) return;

    float x = pos[3 * p + 0], y = pos[3 * p + 1], z = pos[3 * p + 2];
    float r    = sqrtf(x * x + y * y + z * z) + 1e-12f;
    float invr = 1.0f / r;
    float xs = x * invr, ys = y * invr, ct = z * invr;

    float e1 = expf(-r), e2 = expf(-0.5f * r);
    float e3 = expf(-r * (1.0f / 3.0f)), e4 = expf(-0.25f * r);

    const float C00 = 0.28209479177387814f;
    const float K10 = 0.4886025119029199f;
    const float C21 = 1.0925484305920792f;
    const float C22 = 0.5462742152960396f;
    const float C20 = 0.31539156525252005f;

    float Y1m1 = -K10 * ys, Y10 = K10 * ct, Y1p1 = -K10 * xs;
    float Y2m2 =  C21 * xs * ys;
    float Y2m1 = -C21 * ys * ct;
    float Y20  =  C20 * (3.0f * ct * ct - 1.0f);
    float Y2p1 = -C21 * xs * ct;
    float Y2p2 =  C22 * (xs * xs - ys * ys);

    float R10 = 2.0f * e1;
    float R20 = 0.35355339059327373f * e2 * (2.0f - r);
    float R21 = 0.2041241452319315f  * e2 * r;

    float rho3 = (2.0f / 3.0f) * r;
    float R30 = 0.1283000598199168f   * e3 * (3.0f - 3.0f * rho3 + 0.5f * rho3 * rho3);
    float R31 = 0.045360921162019494f * e3 * rho3 * (4.0f - rho3);
    float R32 = 0.02028602242947916f  * e3 * rho3 * rho3;

    float rho4 = 0.5f * r;
    float R40 = 0.0625f * e4 *
                (4.0f - 6.0f * rho4 + 2.0f * rho4 * rho4 - rho4 * rho4 * rho4 * (1.0f / 6.0f));
    float R41 = 0.016137430609197573f * e4 * rho4 * (10.0f - 5.0f * rho4 + 0.5f * rho4 * rho4);
    float R42 = 0.004658474194686761f * e4 * rho4 * rho4 * (6.0f - rho4);

    float v[NBASIS];
    v[0]  = R10 * C00;
    v[1]  = R20 * C00;
    v[2]  = R21 * Y1m1;  v[3]  = R21 * Y10;  v[4]  = R21 * Y1p1;
    v[5]  = R30 * C00;
    v[6]  = R31 * Y1m1;  v[7]  = R31 * Y10;  v[8]  = R31 * Y1p1;
    v[9]  = R32 * Y2m2;  v[10] = R32 * Y2m1; v[11] = R32 * Y20;
    v[12] = R32 * Y2p1;  v[13] = R32 * Y2p2;
    v[14] = R40 * C00;
    v[15] = R41 * Y1m1;  v[16] = R41 * Y10;  v[17] = R41 * Y1p1;
    v[18] = R42 * Y2m2;  v[19] = R42 * Y2m1; v[20] = R42 * Y20;
    v[21] = R42 * Y2p1;  v[22] = R42 * Y2p2;

#pragma unroll
    for (int k = 0; k < NBASIS; k++) g_poly[k * NPTS + p] = v[k];
}

// ---------------------------------------------------------------------------
// Kernel 2: out(4096 x 32768) = coeff(4096 x 23) @ poly(23 x 32768)
// f32x2 GEMM with ROW-paired accumulators (no inner-loop operand dup):
//   acc{r,r+1}[pt] += {c_r[k], c_{r+1}[k]} * {p,p}
//   - coeff tile in smem K-MAJOR (cs[k][128 rows]): a float4 broadcast load
//     yields 4 adjacent rows' coefficients; its (x,y)/(z,w) halves are
//     already even-aligned register pairs -> zero packing MOVs
//   - poly duplicated {p,p} ONCE per thread before the 128-row loop
//   - 2 points/thread (p0, p0+256), 4-row steps -> 4 independent fma2 chains
//   - stores: STG.32, each one a contiguous 128B warp transaction
// ---------------------------------------------------------------------------
#define TPB   256
#define PT    512    // points per block (2 per thread)
#define RT    128    // coefficient rows per block

__device__ __forceinline__ float2 fma2(float2 a, float2 b, float2 c) {
    unsigned long long ua, ub, uc;
    memcpy(&ua, &a, 8); memcpy(&ub, &b, 8); memcpy(&uc, &c, 8);
    asm("fma.rn.f32x2 %0, %1, %2, %0;" : "+l"(uc) : "l"(ua), "l"(ub));
    float2 d; memcpy(&d, &uc, 8);
    return d;
}

__global__ __launch_bounds__(TPB, 2) void gemm_kernel(const float* __restrict__ coeff,
                                                      float* __restrict__ out) {
    __shared__ float cs[NBASIS * RT];   // k-major: cs[k*RT + row], 11.5 KB

    int tid = threadIdx.x;
    int p0  = blockIdx.x * PT + tid;      // point 0
    int p1  = p0 + TPB;                   // point 1 (256 apart)
    int r0  = blockIdx.y * RT;

    // Stage coefficient tile transposed to k-major.
    for (int i = tid; i < NBASIS * RT; i += TPB) {
        int k  = i / RT;
        int rr = i - k * RT;
        cs[i] = coeff[(r0 + rr) * NBASIS + k];
    }

    // Poly values for this thread's 2 points, duplicated ONCE into f32x2.
    float2 pp0[NBASIS], pp1[NBASIS];
#pragma unroll
    for (int k = 0; k < NBASIS; k++) {
        float a = g_poly[k * NPTS + p0];
        float b = g_poly[k * NPTS + p1];
        pp0[k] = make_float2(a, a);
        pp1[k] = make_float2(b, b);
    }
    __syncthreads();

    for (int rj = 0; rj < RT; rj += 4) {
        float2 a00 = make_float2(0.0f, 0.0f);   // p0, rows rj, rj+1
        float2 a01 = make_float2(0.0f, 0.0f);   // p0, rows rj+2, rj+3
        float2 a10 = make_float2(0.0f, 0.0f);   // p1, rows rj, rj+1
        float2 a11 = make_float2(0.0f, 0.0f);   // p1, rows rj+2, rj+3
#pragma unroll
        for (int k = 0; k < NBASIS; k++) {
            float4 c4 = *reinterpret_cast<const float4*>(&cs[k * RT + rj]);  // LDS.128 broadcast
            float2 cA = make_float2(c4.x, c4.y);   // rows rj, rj+1 (even reg pair)
            float2 cB = make_float2(c4.z, c4.w);   // rows rj+2, rj+3
            a00 = fma2(cA, pp0[k], a00);
            a10 = fma2(cA, pp1[k], a10);
            a01 = fma2(cB, pp0[k], a01);
            a11 = fma2(cB, pp1[k], a11);
        }
        float* ob = out + (size_t)(r0 + rj) * NPTS;
        __stcs(ob + p0,                    a00.x);
        __stcs(ob + p1,                    a10.x);
        __stcs(ob + (size_t)NPTS     + p0, a00.y);
        __stcs(ob + (size_t)NPTS     + p1, a10.y);
        __stcs(ob + (size_t)2 * NPTS + p0, a01.x);
        __stcs(ob + (size_t)2 * NPTS + p1, a11.x);
        __stcs(ob + (size_t)3 * NPTS + p0, a01.y);
        __stcs(ob + (size_t)3 * NPTS + p1, a11.y);
    }
}

// ---------------------------------------------------------------------------
// Launch: [0] position (8*4096*3 f32), [1] coefficients (64*64*23 f32).
// Output: (64,64,8,4096) f32 = out[row][point].
// ---------------------------------------------------------------------------
extern "C" void kernel_launch(void* const* d_in, const int* in_sizes, int n_in,
                              void* d_out, int out_size) {
    const float* pos   = (const float*)d_in[0];
    const float* coeff = (const float*)d_in[1];
    float* out = (float*)d_out;

    basis_kernel<<<NPTS / 256, 256>>>(pos);

    dim3 grid(NPTS / PT, NROWS / RT);   // (64, 32)
    gemm_kernel<<<grid, TPB>>>(coeff, out);
}